// round 13
// baseline (speedup 1.0000x reference)
#include <cuda_runtime.h>
#include <cuda_fp16.h>
#include <cstdint>

#define NUM_CLASSES 100000
#define BATCH 512
#define EMBED 512
#define NTILES 782          // class tiles of 128

#define S_SCALE 64.0f
#define COS_M 0.8775825618903728f
#define SIN_M 0.479425538604203f
#define TH_V (-0.8775825618903728f)
#define MM_V 0.23971276930210156f

// scratch (no allocations allowed)
__device__ __half g_wh[(size_t)NUM_CLASSES * EMBED];  // fp16(w / ||w||)
__device__ __half g_xh[BATCH * EMBED];                // fp16(x)
__device__ float  g_pmax[(size_t)BATCH * NTILES];     // LSE partial max
__device__ float  g_psum[(size_t)BATCH * NTILES];     // LSE partial sumexp
__device__ float  g_rownll[BATCH];
__device__ int    g_label[BATCH];

// ---------------------------------------------------------------------------
// K0: label dtype autodetect (int64 vs int32) + materialize int32 labels.
// ---------------------------------------------------------------------------
__global__ void label_kernel(const int* __restrict__ raw) {
    __shared__ int s_or[16];
    int tid = threadIdx.x;
    int v = (tid & 1) ? raw[tid] : 0;
#pragma unroll
    for (int o = 16; o; o >>= 1) v |= __shfl_xor_sync(0xffffffffu, v, o);
    if ((tid & 31) == 0) s_or[tid >> 5] = v;
    __syncthreads();
    if (tid < 16) {
        int w = s_or[tid];
#pragma unroll
        for (int o = 8; o; o >>= 1) w |= __shfl_xor_sync(0xffffu, w, o);
        if (tid == 0) s_or[0] = w;
    }
    __syncthreads();
    bool is64 = (s_or[0] == 0);
    g_label[tid] = is64 ? raw[2 * tid] : raw[tid];
}

// ---------------------------------------------------------------------------
// K1a: W prep — normalize rows (fp32) + fp16 RNE convert. One warp per row.
// ---------------------------------------------------------------------------
__global__ void wprep_kernel(const float* __restrict__ w) {
    int gw   = (blockIdx.x * blockDim.x + threadIdx.x) >> 5;
    int lane = threadIdx.x & 31;
    if (gw >= NUM_CLASSES) return;
    const float4* row = (const float4*)(w + (size_t)gw * EMBED);
    float4 v[4];
    float s = 0.f;
#pragma unroll
    for (int i = 0; i < 4; i++) {
        v[i] = row[lane + i * 32];
        s += v[i].x * v[i].x + v[i].y * v[i].y + v[i].z * v[i].z + v[i].w * v[i].w;
    }
#pragma unroll
    for (int o = 16; o; o >>= 1) s += __shfl_xor_sync(0xffffffffu, s, o);
    float rn = 1.0f / fmaxf(__fsqrt_rn(s), 1e-12f);
    __half2* dst = (__half2*)(g_wh + (size_t)gw * EMBED);
#pragma unroll
    for (int i = 0; i < 4; i++) {
        int g2 = (lane + i * 32) * 2;
        dst[g2 + 0] = __floats2half2_rn(v[i].x * rn, v[i].y * rn);
        dst[g2 + 1] = __floats2half2_rn(v[i].z * rn, v[i].w * rn);
    }
}

// K1b: X prep — fp16 RNE convert.
__global__ void xprep_kernel(const float* __restrict__ x) {
    int i = blockIdx.x * 256 + threadIdx.x;   // over BATCH*EMBED/2
    float2 v = ((const float2*)x)[i];
    ((__half2*)g_xh)[i] = __floats2half2_rn(v.x, v.y);
}

// ---------------------------------------------------------------------------
// K2: fp16 GEMM (mma.sync m16n8k16, fp32 accum, ldmatrix) + ArcFace epilogue
//     + FUSED per-tile logsumexp partials (saves K3's 205MB re-read).
// CTA tile 64x128, 128 threads (4 warps), warp tile 64x32. BK=64, 2-stage
// cp.async pipeline with intra-warp fragment double-buffering.
// ---------------------------------------------------------------------------
#define BM 64
#define BN 128
#define BK 64
#define ST 72                // halves per smem row (64 + 8 pad), 144B stride
#define NKT (EMBED / BK)     // 8
#define A_H (BM * ST)        // 4608 halves
#define B_H (BN * ST)        // 9216 halves
#define STAGE_H (A_H + B_H)  // 13824 halves
#define DSMEM_BYTES (2 * STAGE_H * 2)   // 55296 B

extern __shared__ __half dsm[];

__device__ __forceinline__ uint32_t smem_u32(const void* p) {
    return (uint32_t)__cvta_generic_to_shared(p);
}
__device__ __forceinline__ void cp_async16(void* smem, const void* gsrc, bool pred) {
    uint32_t sa = smem_u32(smem);
    int sz = pred ? 16 : 0;
    asm volatile("cp.async.cg.shared.global [%0], [%1], 16, %2;\n"
                 :: "r"(sa), "l"(gsrc), "r"(sz));
}
__device__ __forceinline__ void ldsm_x4(uint32_t& r0, uint32_t& r1,
                                        uint32_t& r2, uint32_t& r3, uint32_t addr) {
    asm volatile("ldmatrix.sync.aligned.m8n8.x4.shared.b16 {%0,%1,%2,%3}, [%4];"
                 : "=r"(r0), "=r"(r1), "=r"(r2), "=r"(r3) : "r"(addr));
}
__device__ __forceinline__ void mma_f16(float* d, const uint32_t* a, const uint32_t* b) {
    asm volatile(
        "mma.sync.aligned.m16n8k16.row.col.f32.f16.f16.f32 "
        "{%0,%1,%2,%3}, {%4,%5,%6,%7}, {%8,%9}, {%0,%1,%2,%3};\n"
        : "+f"(d[0]), "+f"(d[1]), "+f"(d[2]), "+f"(d[3])
        : "r"(a[0]), "r"(a[1]), "r"(a[2]), "r"(a[3]), "r"(b[0]), "r"(b[1]));
}
__device__ __forceinline__ float arcface_val(float c, bool is_label) {
    if (is_label) {
        float s2 = fminf(fmaxf(1.0f - c * c, 0.0f), 1.0f);
        float phi = c * COS_M - sqrtf(s2) * SIN_M;
        c = (c > TH_V) ? phi : (c - MM_V);
    }
    return c * S_SCALE;
}
// guarded logsumexp-partial merge: identity (-inf, 0)
__device__ __forceinline__ void lse_merge(float& mx, float& sm, float omx, float osm) {
    float nm = fmaxf(mx, omx);
    float t1 = (sm  > 0.f) ? sm  * __expf(mx  - nm) : 0.f;
    float t2 = (osm > 0.f) ? osm * __expf(omx - nm) : 0.f;
    mx = nm; sm = t1 + t2;
}

__global__ void __launch_bounds__(128, 3)
arcface_gemm_f16(float* __restrict__ out) {
    const int m0 = blockIdx.x * BM;   // 8 batch tiles (fast dim -> W reuse in L2)
    const int n0 = blockIdx.y * BN;   // 782 class tiles
    const int tid  = threadIdx.x;
    const int wn   = tid >> 5, lane = tid & 31;   // 4 warps across N
    const int grp = lane >> 2, tig = lane & 3;

    float acc[4][4][4];
#pragma unroll
    for (int i = 0; i < 4; i++)
#pragma unroll
        for (int j = 0; j < 4; j++)
#pragma unroll
            for (int k = 0; k < 4; k++) acc[i][j][k] = 0.f;

    // ldmatrix per-lane byte offsets within a stage buffer
    const int g8 = lane >> 3, rw = lane & 7;
    const uint32_t a_off = (uint32_t)((((g8 & 1) * 8 + rw) * ST + (g8 >> 1) * 8) * 2);
    const uint32_t b_off0 = (uint32_t)(A_H * 2 +
                    (((wn * 32 + (g8 >> 1) * 8 + rw) * ST + (g8 & 1) * 8) * 2));
    const uint32_t b_off1 = b_off0 + 16 * ST * 2;

    // loader: A 512 + B 1024 chunks of 16B over 128 threads -> 12 each
    auto load_tiles = [&](int kt) {
        __half* stg = dsm + (kt & 1) * STAGE_H;
#pragma unroll
        for (int i = 0; i < 4; i++) {      // A: 64 rows x 8 chunks
            int id  = tid + i * 128;
            int row = id >> 3, c8 = (id & 7) * 8;
            cp_async16(stg + row * ST + c8,
                       g_xh + (size_t)(m0 + row) * EMBED + kt * BK + c8, true);
        }
#pragma unroll
        for (int i = 0; i < 8; i++) {      // B: 128 rows x 8 chunks
            int id  = tid + i * 128;
            int row = id >> 3, c8 = (id & 7) * 8;
            bool p = (n0 + row) < NUM_CLASSES;
            cp_async16(stg + A_H + row * ST + c8,
                       g_wh + (size_t)(n0 + row) * EMBED + kt * BK + c8, p);
        }
        asm volatile("cp.async.commit_group;\n");
    };

    uint32_t af[2][4][4], bf[2][4][2];

    auto frag_load = [&](uint32_t Sb, int kk, int slot) {
        const uint32_t kb = kk * 32;   // 16 halves = 32 bytes
        ldsm_x4(bf[slot][0][0], bf[slot][0][1], bf[slot][1][0], bf[slot][1][1],
                Sb + b_off0 + kb);
        ldsm_x4(bf[slot][2][0], bf[slot][2][1], bf[slot][3][0], bf[slot][3][1],
                Sb + b_off1 + kb);
#pragma unroll
        for (int mt = 0; mt < 4; mt++)
            ldsm_x4(af[slot][mt][0], af[slot][mt][1], af[slot][mt][2], af[slot][mt][3],
                    Sb + a_off + mt * (16 * ST * 2) + kb);
    };

    load_tiles(0);
    load_tiles(1);

    for (int kt = 0; kt < NKT; kt++) {
        if (kt < NKT - 1) asm volatile("cp.async.wait_group 1;\n");
        else              asm volatile("cp.async.wait_group 0;\n");
        __syncthreads();   // tile kt visible to all warps

        const uint32_t Sb = smem_u32(dsm + (kt & 1) * STAGE_H);
        frag_load(Sb, 0, 0);
#pragma unroll
        for (int kk = 0; kk < BK / 16; kk++) {
            const int cur = kk & 1, nxt = cur ^ 1;
            if (kk + 1 < BK / 16) frag_load(Sb, kk + 1, nxt);  // overlap w/ MMAs
#pragma unroll
            for (int mt = 0; mt < 4; mt++)
#pragma unroll
                for (int nt = 0; nt < 4; nt++)
                    mma_f16(acc[mt][nt], af[cur][mt], bf[cur][nt]);
        }
        __syncthreads();   // all reads of buf kt&1 done before overwrite
        if (kt + 2 < NKT) load_tiles(kt + 2);
    }

    // Epilogue: ArcFace margin + store + fused LSE partials.
    // dsm is free after the final __syncthreads above.
    float* s_pm = (float*)dsm;          // [4 warps][64 rows]
    float* s_ps = (float*)dsm + 256;
#pragma unroll
    for (int mt = 0; mt < 4; mt++) {
#pragma unroll
        for (int hi = 0; hi < 2; hi++) {
            int m   = m0 + mt * 16 + hi * 8 + grp;
            int lbl = g_label[m];
            float mx = -INFINITY, sm = 0.f;
#pragma unroll
            for (int nt = 0; nt < 4; nt++) {
                int n = n0 + wn * 32 + nt * 8 + 2 * tig;
                float* a = acc[mt][nt];
#pragma unroll
                for (int c2 = 0; c2 < 2; c2++) {
                    int nn = n + c2;
                    if (nn < NUM_CLASSES) {
                        float c = arcface_val(a[hi * 2 + c2], nn == lbl);
                        out[(size_t)m * NUM_CLASSES + nn] = c;
                        if (c > mx) { sm *= __expf(mx - c); mx = c; }
                        sm += __expf(c - mx);
                    }
                }
            }
            // reduce across tig lanes (lane bits 0..1) sharing this row
#pragma unroll
            for (int o = 1; o <= 2; o <<= 1) {
                float omx = __shfl_xor_sync(0xffffffffu, mx, o);
                float osm = __shfl_xor_sync(0xffffffffu, sm, o);
                lse_merge(mx, sm, omx, osm);
            }
            if (tig == 0) {
                int r = mt * 16 + hi * 8 + grp;
                s_pm[wn * 64 + r] = mx;
                s_ps[wn * 64 + r] = sm;
            }
        }
    }
    __syncthreads();
    if (tid < 64) {
        float mx = s_pm[tid], sm = s_ps[tid];
#pragma unroll
        for (int w = 1; w < 4; w++)
            lse_merge(mx, sm, s_pm[w * 64 + tid], s_ps[w * 64 + tid]);
        g_pmax[(size_t)(m0 + tid) * NTILES + blockIdx.y] = mx;
        g_psum[(size_t)(m0 + tid) * NTILES + blockIdx.y] = sm;
    }
}

// ---------------------------------------------------------------------------
// K3': merge 782 LSE partials per row (3.2MB total) -> per-row NLL.
// ---------------------------------------------------------------------------
__global__ void lse_reduce_kernel(const float* __restrict__ out) {
    const int row = blockIdx.x;
    const int tid = threadIdx.x;
    const float* pm = g_pmax + (size_t)row * NTILES;
    const float* ps = g_psum + (size_t)row * NTILES;

    float mx = -INFINITY, sm = 0.f;
    for (int t = tid; t < NTILES; t += 256) {
        float omx = pm[t], osm = ps[t];
        float nm = fmaxf(mx, omx);
        float t1 = (sm  > 0.f) ? sm  * __expf(mx  - nm) : 0.f;
        float t2 = (osm > 0.f) ? osm * __expf(omx - nm) : 0.f;
        mx = nm; sm = t1 + t2;
    }
    __shared__ float spm[256], sps[256];
    spm[tid] = mx; sps[tid] = sm;
    __syncthreads();
    for (int o = 128; o; o >>= 1) {
        if (tid < o) {
            float m1 = spm[tid], s1 = sps[tid];
            float m2 = spm[tid + o], s2 = sps[tid + o];
            float nm = fmaxf(m1, m2);
            float t1 = (s1 > 0.f) ? s1 * __expf(m1 - nm) : 0.f;
            float t2 = (s2 > 0.f) ? s2 * __expf(m2 - nm) : 0.f;
            spm[tid] = nm; sps[tid] = t1 + t2;
        }
        __syncthreads();
    }
    if (tid == 0) {
        float logZ = spm[0] + __logf(sps[0]);
        int lbl = g_label[row];
        g_rownll[row] = logZ - out[(size_t)row * NUM_CLASSES + lbl];
    }
}

// ---------------------------------------------------------------------------
// K4: loss = mean(rownll).
// ---------------------------------------------------------------------------
__global__ void loss_kernel(float* __restrict__ out, int out_size) {
    __shared__ float sm[BATCH];
    sm[threadIdx.x] = g_rownll[threadIdx.x];
    __syncthreads();
    for (int o = 256; o; o >>= 1) {
        if (threadIdx.x < o) sm[threadIdx.x] += sm[threadIdx.x + o];
        __syncthreads();
    }
    if (threadIdx.x == 0) {
        long long total = (long long)BATCH * NUM_CLASSES;
        if ((long long)out_size > total)
            out[total] = sm[0] * (1.0f / BATCH);
    }
}

// ---------------------------------------------------------------------------
extern "C" void kernel_launch(void* const* d_in, const int* in_sizes, int n_in,
                              void* d_out, int out_size) {
    const float* X        = (const float*)d_in[0];
    const int*   labelRaw = (const int*)d_in[1];
    const float* W        = (const float*)d_in[2];
    float* out = (float*)d_out;

    static bool attr_done = false;
    if (!attr_done) {
        cudaFuncSetAttribute(arcface_gemm_f16,
                             cudaFuncAttributeMaxDynamicSharedMemorySize, DSMEM_BYTES);
        attr_done = true;
    }

    label_kernel<<<1, BATCH>>>(labelRaw);
    xprep_kernel<<<BATCH * EMBED / 512, 256>>>(X);
    wprep_kernel<<<NUM_CLASSES / 8, 256>>>(W);

    dim3 grid(BATCH / BM, NTILES);   // (8, 782)
    arcface_gemm_f16<<<grid, 128, DSMEM_BYTES>>>(out);

    lse_reduce_kernel<<<BATCH, 256>>>(out);
    loss_kernel<<<1, BATCH>>>(out, out_size);
}

// round 14
// speedup vs baseline: 1.0797x; 1.0797x over previous
#include <cuda_runtime.h>
#include <cuda_fp16.h>
#include <cstdint>

#define NUM_CLASSES 100000
#define BATCH 512
#define EMBED 512
#define LSE_SPLITS 4
#define SPLIT_N (NUM_CLASSES / LSE_SPLITS)   // 25000

#define S_SCALE 64.0f
#define COS_M 0.8775825618903728f
#define SIN_M 0.479425538604203f
#define TH_V (-0.8775825618903728f)
#define MM_V 0.23971276930210156f

// scratch (no allocations allowed)
__device__ __half g_wh[(size_t)NUM_CLASSES * EMBED];  // fp16(w / ||w||)
__device__ __half g_xh[BATCH * EMBED];                // fp16(x)
__device__ float  g_pmax[BATCH * LSE_SPLITS];         // LSE partial max
__device__ float  g_psum[BATCH * LSE_SPLITS];         // LSE partial sumexp
__device__ int    g_label[BATCH];

// ---------------------------------------------------------------------------
// K0: label dtype autodetect (int64 vs int32) + materialize int32 labels.
// ---------------------------------------------------------------------------
__global__ void label_kernel(const int* __restrict__ raw) {
    __shared__ int s_or[16];
    int tid = threadIdx.x;
    int v = (tid & 1) ? raw[tid] : 0;
#pragma unroll
    for (int o = 16; o; o >>= 1) v |= __shfl_xor_sync(0xffffffffu, v, o);
    if ((tid & 31) == 0) s_or[tid >> 5] = v;
    __syncthreads();
    if (tid < 16) {
        int w = s_or[tid];
#pragma unroll
        for (int o = 8; o; o >>= 1) w |= __shfl_xor_sync(0xffffu, w, o);
        if (tid == 0) s_or[0] = w;
    }
    __syncthreads();
    bool is64 = (s_or[0] == 0);
    g_label[tid] = is64 ? raw[2 * tid] : raw[tid];
}

// ---------------------------------------------------------------------------
// K1a: W prep — normalize rows (fp32) + fp16 RNE convert. One warp per row.
// ---------------------------------------------------------------------------
__global__ void wprep_kernel(const float* __restrict__ w) {
    int gw   = (blockIdx.x * blockDim.x + threadIdx.x) >> 5;
    int lane = threadIdx.x & 31;
    if (gw >= NUM_CLASSES) return;
    const float4* row = (const float4*)(w + (size_t)gw * EMBED);
    float4 v[4];
    float s = 0.f;
#pragma unroll
    for (int i = 0; i < 4; i++) {
        v[i] = row[lane + i * 32];
        s += v[i].x * v[i].x + v[i].y * v[i].y + v[i].z * v[i].z + v[i].w * v[i].w;
    }
#pragma unroll
    for (int o = 16; o; o >>= 1) s += __shfl_xor_sync(0xffffffffu, s, o);
    float rn = 1.0f / fmaxf(__fsqrt_rn(s), 1e-12f);
    __half2* dst = (__half2*)(g_wh + (size_t)gw * EMBED);
#pragma unroll
    for (int i = 0; i < 4; i++) {
        int g2 = (lane + i * 32) * 2;
        dst[g2 + 0] = __floats2half2_rn(v[i].x * rn, v[i].y * rn);
        dst[g2 + 1] = __floats2half2_rn(v[i].z * rn, v[i].w * rn);
    }
}

// K1b: X prep — fp16 RNE convert.
__global__ void xprep_kernel(const float* __restrict__ x) {
    int i = blockIdx.x * 256 + threadIdx.x;   // over BATCH*EMBED/2
    float2 v = ((const float2*)x)[i];
    ((__half2*)g_xh)[i] = __floats2half2_rn(v.x, v.y);
}

// ---------------------------------------------------------------------------
// K2: fp16 GEMM (mma.sync m16n8k16, fp32 accum, ldmatrix) + ArcFace epilogue.
// R12-best config: CTA 64x128, 128 threads, warp tile 64x32, BK=64,
// 2-stage cp.async + intra-warp fragment double-buffering.
// (Legacy HMMA.F32 issue interval ~18.6 cyc/SMSP on sm_103a == measured
//  floor; tcgen05 blocked by compute_103 PTX target.)
// ---------------------------------------------------------------------------
#define BM 64
#define BN 128
#define BK 64
#define ST 72                // halves per smem row (64 + 8 pad), 144B stride
#define NKT (EMBED / BK)     // 8
#define A_H (BM * ST)        // 4608 halves
#define B_H (BN * ST)        // 9216 halves
#define STAGE_H (A_H + B_H)  // 13824 halves
#define DSMEM_BYTES (2 * STAGE_H * 2)   // 55296 B

extern __shared__ __half dsm[];

__device__ __forceinline__ uint32_t smem_u32(const void* p) {
    return (uint32_t)__cvta_generic_to_shared(p);
}
__device__ __forceinline__ void cp_async16(void* smem, const void* gsrc, bool pred) {
    uint32_t sa = smem_u32(smem);
    int sz = pred ? 16 : 0;
    asm volatile("cp.async.cg.shared.global [%0], [%1], 16, %2;\n"
                 :: "r"(sa), "l"(gsrc), "r"(sz));
}
__device__ __forceinline__ void ldsm_x4(uint32_t& r0, uint32_t& r1,
                                        uint32_t& r2, uint32_t& r3, uint32_t addr) {
    asm volatile("ldmatrix.sync.aligned.m8n8.x4.shared.b16 {%0,%1,%2,%3}, [%4];"
                 : "=r"(r0), "=r"(r1), "=r"(r2), "=r"(r3) : "r"(addr));
}
__device__ __forceinline__ void mma_f16(float* d, const uint32_t* a, const uint32_t* b) {
    asm volatile(
        "mma.sync.aligned.m16n8k16.row.col.f32.f16.f16.f32 "
        "{%0,%1,%2,%3}, {%4,%5,%6,%7}, {%8,%9}, {%0,%1,%2,%3};\n"
        : "+f"(d[0]), "+f"(d[1]), "+f"(d[2]), "+f"(d[3])
        : "r"(a[0]), "r"(a[1]), "r"(a[2]), "r"(a[3]), "r"(b[0]), "r"(b[1]));
}
__device__ __forceinline__ float arcface_val(float c, bool is_label) {
    if (is_label) {
        float s2 = fminf(fmaxf(1.0f - c * c, 0.0f), 1.0f);
        float phi = c * COS_M - sqrtf(s2) * SIN_M;
        c = (c > TH_V) ? phi : (c - MM_V);
    }
    return c * S_SCALE;
}

__global__ void __launch_bounds__(128, 3)
arcface_gemm_f16(float* __restrict__ out) {
    const int m0 = blockIdx.x * BM;   // 8 batch tiles (fast dim -> W reuse in L2)
    const int n0 = blockIdx.y * BN;   // 782 class tiles
    const int tid  = threadIdx.x;
    const int wn   = tid >> 5, lane = tid & 31;   // 4 warps across N
    const int grp = lane >> 2, tig = lane & 3;

    float acc[4][4][4];
#pragma unroll
    for (int i = 0; i < 4; i++)
#pragma unroll
        for (int j = 0; j < 4; j++)
#pragma unroll
            for (int k = 0; k < 4; k++) acc[i][j][k] = 0.f;

    // ldmatrix per-lane byte offsets within a stage buffer
    const int g8 = lane >> 3, rw = lane & 7;
    const uint32_t a_off = (uint32_t)((((g8 & 1) * 8 + rw) * ST + (g8 >> 1) * 8) * 2);
    const uint32_t b_off0 = (uint32_t)(A_H * 2 +
                    (((wn * 32 + (g8 >> 1) * 8 + rw) * ST + (g8 & 1) * 8) * 2));
    const uint32_t b_off1 = b_off0 + 16 * ST * 2;

    // loader: A 512 + B 1024 chunks of 16B over 128 threads -> 12 each
    auto load_tiles = [&](int kt) {
        __half* stg = dsm + (kt & 1) * STAGE_H;
#pragma unroll
        for (int i = 0; i < 4; i++) {      // A: 64 rows x 8 chunks
            int id  = tid + i * 128;
            int row = id >> 3, c8 = (id & 7) * 8;
            cp_async16(stg + row * ST + c8,
                       g_xh + (size_t)(m0 + row) * EMBED + kt * BK + c8, true);
        }
#pragma unroll
        for (int i = 0; i < 8; i++) {      // B: 128 rows x 8 chunks
            int id  = tid + i * 128;
            int row = id >> 3, c8 = (id & 7) * 8;
            bool p = (n0 + row) < NUM_CLASSES;
            cp_async16(stg + A_H + row * ST + c8,
                       g_wh + (size_t)(n0 + row) * EMBED + kt * BK + c8, p);
        }
        asm volatile("cp.async.commit_group;\n");
    };

    uint32_t af[2][4][4], bf[2][4][2];

    auto frag_load = [&](uint32_t Sb, int kk, int slot) {
        const uint32_t kb = kk * 32;   // 16 halves = 32 bytes
        ldsm_x4(bf[slot][0][0], bf[slot][0][1], bf[slot][1][0], bf[slot][1][1],
                Sb + b_off0 + kb);
        ldsm_x4(bf[slot][2][0], bf[slot][2][1], bf[slot][3][0], bf[slot][3][1],
                Sb + b_off1 + kb);
#pragma unroll
        for (int mt = 0; mt < 4; mt++)
            ldsm_x4(af[slot][mt][0], af[slot][mt][1], af[slot][mt][2], af[slot][mt][3],
                    Sb + a_off + mt * (16 * ST * 2) + kb);
    };

    load_tiles(0);
    load_tiles(1);

    for (int kt = 0; kt < NKT; kt++) {
        if (kt < NKT - 1) asm volatile("cp.async.wait_group 1;\n");
        else              asm volatile("cp.async.wait_group 0;\n");
        __syncthreads();   // tile kt visible to all warps

        const uint32_t Sb = smem_u32(dsm + (kt & 1) * STAGE_H);
        frag_load(Sb, 0, 0);
#pragma unroll
        for (int kk = 0; kk < BK / 16; kk++) {
            const int cur = kk & 1, nxt = cur ^ 1;
            if (kk + 1 < BK / 16) frag_load(Sb, kk + 1, nxt);  // overlap w/ MMAs
#pragma unroll
            for (int mt = 0; mt < 4; mt++)
#pragma unroll
                for (int nt = 0; nt < 4; nt++)
                    mma_f16(acc[mt][nt], af[cur][mt], bf[cur][nt]);
        }
        __syncthreads();   // all reads of buf kt&1 done before overwrite
        if (kt + 2 < NKT) load_tiles(kt + 2);
    }

    // Epilogue: ArcFace margin at label column, * S.
#pragma unroll
    for (int mt = 0; mt < 4; mt++) {
        int m_lo = m0 + mt * 16 + grp;
        int m_hi = m_lo + 8;
        int lbl_lo = g_label[m_lo];
        int lbl_hi = g_label[m_hi];
#pragma unroll
        for (int nt = 0; nt < 4; nt++) {
            int n = n0 + wn * 32 + nt * 8 + 2 * tig;
            float* a = acc[mt][nt];
            if (n < NUM_CLASSES) {
                out[(size_t)m_lo * NUM_CLASSES + n] = arcface_val(a[0], n == lbl_lo);
                out[(size_t)m_hi * NUM_CLASSES + n] = arcface_val(a[2], n == lbl_hi);
            }
            if (n + 1 < NUM_CLASSES) {
                out[(size_t)m_lo * NUM_CLASSES + n + 1] = arcface_val(a[1], (n + 1) == lbl_lo);
                out[(size_t)m_hi * NUM_CLASSES + n + 1] = arcface_val(a[3], (n + 1) == lbl_hi);
            }
        }
    }
}

// ---------------------------------------------------------------------------
// K3: partial logsumexp — 4 blocks per row (2048 blocks, fine waves),
// streaming loads (__ldcs), partial (max, sumexp) to global.
// ---------------------------------------------------------------------------
__global__ void lse_part_kernel(const float* __restrict__ logits) {
    const int row = blockIdx.x >> 2;
    const int spl = blockIdx.x & 3;
    const int tid = threadIdx.x;
    const float4* p = (const float4*)(logits + (size_t)row * NUM_CLASSES
                                      + spl * SPLIT_N);
    const int n4 = SPLIT_N / 4;   // 6250

    float m = -INFINITY, s = 0.f;
    for (int i = tid; i < n4; i += 256) {
        float4 v = __ldcs(p + i);
        float mx = fmaxf(fmaxf(v.x, v.y), fmaxf(v.z, v.w));
        if (mx > m) { s *= __expf(m - mx); m = mx; }
        s += __expf(v.x - m) + __expf(v.y - m) + __expf(v.z - m) + __expf(v.w - m);
    }

    __shared__ float sm[256];
    __shared__ float ss[256];
    sm[tid] = m; ss[tid] = s;
    __syncthreads();
    for (int o = 128; o; o >>= 1) {
        if (tid < o) {
            float m1 = sm[tid], s1 = ss[tid];
            float m2 = sm[tid + o], s2 = ss[tid + o];
            float mm = fmaxf(m1, m2);
            float t1 = (s1 > 0.f) ? s1 * __expf(m1 - mm) : 0.f;
            float t2 = (s2 > 0.f) ? s2 * __expf(m2 - mm) : 0.f;
            sm[tid] = mm; ss[tid] = t1 + t2;
        }
        __syncthreads();
    }
    if (tid == 0) {
        g_pmax[blockIdx.x] = sm[0];
        g_psum[blockIdx.x] = ss[0];
    }
}

// ---------------------------------------------------------------------------
// K4: merge partials -> per-row NLL -> mean loss. One block, 512 threads.
// ---------------------------------------------------------------------------
__global__ void loss_kernel(const float* __restrict__ logits,
                            float* __restrict__ out, int out_size) {
    const int tid = threadIdx.x;   // = row
    float mx = g_pmax[tid * 4], sm = g_psum[tid * 4];
#pragma unroll
    for (int s = 1; s < 4; s++) {
        float omx = g_pmax[tid * 4 + s], osm = g_psum[tid * 4 + s];
        float nm = fmaxf(mx, omx);
        float t1 = (sm  > 0.f) ? sm  * __expf(mx  - nm) : 0.f;
        float t2 = (osm > 0.f) ? osm * __expf(omx - nm) : 0.f;
        mx = nm; sm = t1 + t2;
    }
    float logZ = mx + __logf(sm);
    int lbl = g_label[tid];
    float nll = logZ - logits[(size_t)tid * NUM_CLASSES + lbl];

    __shared__ float red[BATCH];
    red[tid] = nll;
    __syncthreads();
    for (int o = 256; o; o >>= 1) {
        if (tid < o) red[tid] += red[tid + o];
        __syncthreads();
    }
    if (tid == 0) {
        long long total = (long long)BATCH * NUM_CLASSES;
        if ((long long)out_size > total)
            out[total] = red[0] * (1.0f / BATCH);
    }
}

// ---------------------------------------------------------------------------
extern "C" void kernel_launch(void* const* d_in, const int* in_sizes, int n_in,
                              void* d_out, int out_size) {
    const float* X        = (const float*)d_in[0];
    const int*   labelRaw = (const int*)d_in[1];
    const float* W        = (const float*)d_in[2];
    float* out = (float*)d_out;

    static bool attr_done = false;
    if (!attr_done) {
        cudaFuncSetAttribute(arcface_gemm_f16,
                             cudaFuncAttributeMaxDynamicSharedMemorySize, DSMEM_BYTES);
        attr_done = true;
    }

    label_kernel<<<1, BATCH>>>(labelRaw);
    xprep_kernel<<<BATCH * EMBED / 512, 256>>>(X);
    wprep_kernel<<<NUM_CLASSES / 8, 256>>>(W);

    dim3 grid(BATCH / BM, (NUM_CLASSES + BN - 1) / BN);  // (8, 782)
    arcface_gemm_f16<<<grid, 128, DSMEM_BYTES>>>(out);

    lse_part_kernel<<<BATCH * LSE_SPLITS, 256>>>(out);
    loss_kernel<<<1, BATCH>>>(out, out, out_size);
}